// round 7
// baseline (speedup 1.0000x reference)
#include <cuda_runtime.h>

static __device__ __forceinline__ float sigf(float x) {
    return 1.f / (1.f + __expf(-x));
}
static __device__ __forceinline__ float tanh_fast(float x) {
    return 1.f - 2.f / (__expf(2.f * x) + 1.f);
}

typedef unsigned long long ull;
static __device__ __forceinline__ void fma2(ull& d, ull a, ull b) {
    asm("fma.rn.f32x2 %0, %1, %2, %0;" : "+l"(d) : "l"(a), "l"(b));
}
static __device__ __forceinline__ ull bcast2(float x) {
    ull r;
    asm("mov.b64 %0, {%1, %1};" : "=l"(r) : "r"(__float_as_uint(x)));
    return r;
}
static __device__ __forceinline__ void unpack2(ull v, float& lo, float& hi) {
    unsigned a, b;
    asm("mov.b64 {%0, %1}, %2;" : "=r"(a), "=r"(b) : "l"(v));
    lo = __uint_as_float(a); hi = __uint_as_float(b);
}

#define TT 48
#define NAq 35
#define NMe 18
#define NN 53
#define PROW(n) ((n) + ((n) >= NAq ? 1 : 0))
#define XH_STRIDE 100   // [0:32] x, [32:64] h buf0, [64:96] h buf1

// Transposed GRU weights: [ty][mat(6)][k(32)][c(32)]
__device__ float g_wT[2 * 6 * 32 * 32];

__global__ void prep_weights(const float* __restrict__ wih_a, const float* __restrict__ whh_a,
                             const float* __restrict__ wih_m, const float* __restrict__ whh_m) {
    int i = blockIdx.x * 256 + threadIdx.x;
    if (i < 12288) {
        int c = i & 31;
        int k = (i >> 5) & 31;
        int m = (i >> 10) % 6;
        int ty = i / 6144;
        const float* W = (m & 1) ? (ty ? whh_m : whh_a) : (ty ? wih_m : wih_a);
        int gate = m >> 1;
        g_wT[i] = W[(gate * 32 + c) * 32 + k];
    }
}

// dynamic smem carve (floats):
// s_xh    [56][100] : 5600
// s_attri [53][36]  : 1908
// s_e     [2809]    : pad 2812
// s_anc   [2809]
#define DYN_FLOATS (5600 + 1908 + 2812 + 2812)

__global__ __launch_bounds__(256, 3)
void chgat_gru_kernel(
    const float* __restrict__ X_aqi, const float* __restrict__ X_meo,
    const float* __restrict__ ctxf,  const float* __restrict__ adj,
    const float* __restrict__ adjn,
    const float* __restrict__ e_aid, const float* __restrict__ e_amo,
    const float* __restrict__ e_awd, const float* __restrict__ e_ahr,
    const float* __restrict__ e_mwi, const float* __restrict__ e_mid,
    const float* __restrict__ e_mmo, const float* __restrict__ e_mwd,
    const float* __restrict__ e_mhr,
    const float* __restrict__ W_xa,  const float* __restrict__ W_xm,
    const float* __restrict__ W_ua,  const float* __restrict__ W_um,
    const float* __restrict__ a_aa,  const float* __restrict__ a_am,
    const float* __restrict__ a_ma,  const float* __restrict__ a_mm,
    const float* __restrict__ bih_a, const float* __restrict__ bhh_a,
    const float* __restrict__ bih_m, const float* __restrict__ bhh_m,
    const int*   __restrict__ Xae,   const int*   __restrict__ Xme,
    float* __restrict__ out, int B)
{
    extern __shared__ float dynsm[];
    float (*s_xh)[XH_STRIDE] = (float(*)[XH_STRIDE])dynsm;
    float (*s_attri)[36]     = (float(*)[36])(dynsm + 5600);
    float *s_e   = dynsm + 5600 + 1908;
    float *s_anc = s_e + 2812;

    __shared__ float s_in[NN][14];
    __shared__ float s_sd[4][NN];
    __shared__ float s_ctxs[4][NN];
    __shared__ float s_ctxd[4][NN];
    __shared__ float s_as[4][32];
    __shared__ float s_ad[4][32];
    __shared__ unsigned s_mask[NN][2];
    __shared__ float s_brz[2][64];
    __shared__ float s_bni[2][32];
    __shared__ float s_bnh[2][32];
    __shared__ float s_Wua[14*32], s_Wum[14*32], s_Wxa[6*32], s_Wxm[4*32];
    __shared__ float s_emb[300];

    const int tid = threadIdx.x;

    // ---------------- one-time per-block init ----------------
    for (int i = tid; i < 14*32; i += 256) { s_Wua[i] = W_ua[i]; s_Wum[i] = W_um[i]; }
    for (int i = tid; i < 6*32;  i += 256) s_Wxa[i] = W_xa[i];
    for (int i = tid; i < 4*32;  i += 256) s_Wxm[i] = W_xm[i];
    for (int i = tid; i < 64; i += 256) {
        s_brz[0][i] = bih_a[i] + bhh_a[i];
        s_brz[1][i] = bih_m[i] + bhh_m[i];
    }
    for (int i = tid; i < 32; i += 256) {
        s_bni[0][i] = bih_a[64 + i]; s_bnh[0][i] = bhh_a[64 + i];
        s_bni[1][i] = bih_m[64 + i]; s_bnh[1][i] = bhh_m[64 + i];
    }
    for (int i = tid; i < 70; i += 256) s_emb[i]       = e_aid[i];
    for (int i = tid; i < 26; i += 256) s_emb[70 + i]  = e_amo[i];
    for (int i = tid; i < 14; i += 256) s_emb[96 + i]  = e_awd[i];
    for (int i = tid; i < 48; i += 256) s_emb[110 + i] = e_ahr[i];
    for (int i = tid; i < 18; i += 256) s_emb[158 + i] = e_mwi[i];
    for (int i = tid; i < 36; i += 256) s_emb[176 + i] = e_mid[i];
    for (int i = tid; i < 26; i += 256) s_emb[212 + i] = e_mmo[i];
    for (int i = tid; i < 14; i += 256) s_emb[238 + i] = e_mwd[i];
    for (int i = tid; i < 48; i += 256) s_emb[252 + i] = e_mhr[i];
    for (int i = tid; i < 128; i += 256) {
        int v = i >> 5, j = i & 31;
        const float* av = (v == 0) ? a_aa : (v == 1) ? a_am : (v == 2) ? a_ma : a_mm;
        s_as[v][j] = av[j];
        s_ad[v][j] = av[92 + j];
    }
    if (tid < NN) {
        unsigned m0 = 0, m1 = 0;
        for (int j = 0; j < 32; ++j)  if (adj[tid * NN + j] > 0.f) m0 |= (1u << j);
        for (int j = 32; j < NN; ++j) if (adj[tid * NN + j] > 0.f) m1 |= (1u << (j - 32));
        s_mask[tid][0] = m0; s_mask[tid][1] = m1;
    }
    for (int item = tid; item < 4 * NN; item += 256) {
        int v = item / NN, n = item % NN;
        const float* av = (v == 0) ? a_aa : (v == 1) ? a_am : (v == 2) ? a_ma : a_mm;
        float s1 = 0.f, s2 = 0.f;
        for (int c = 0; c < 60; ++c) {
            float cv = ctxf[n * 60 + c];
            s1 = fmaf(cv, av[32 + c], s1);
            s2 = fmaf(cv, av[124 + c], s2);
        }
        s_ctxs[v][n] = s1; s_ctxd[v][n] = s2;
    }
    // adj_norm * a[2D], type-resolved
    for (int idx = tid; idx < NN * NN; idx += 256) {
        int i = idx / NN, j = idx % NN;
        const float* av = (i < NAq) ? ((j < NAq) ? a_aa : a_am)
                                    : ((j < NAq) ? a_ma : a_mm);
        s_anc[idx] = adjn[idx] * av[184];
    }
    __syncthreads();

    const int wid = tid >> 5, lane = tid & 31;
    // GRU tile coords (tid < 216): 27 row-pairs x 8 col-quads
    const int g_rt = tid >> 3, g_cq = tid & 7;
    const int g_p0 = 2 * g_rt, g_p1 = 2 * g_rt + 1;
    const int g_ty = (g_rt < 18) ? 0 : 1;
    const longlong2* g_w2 = (const longlong2*)g_wT + g_ty * 1536 + g_cq;
    // att tile coords (tid < 216): 27 row-pairs x 8 col-quads
    const int a_p = tid >> 3, a_hq = tid & 7;
    const int a_r0 = a_p, a_r1 = a_p + 27;

    for (int b = blockIdx.x; b < B; b += gridDim.x) {
        for (int i = tid; i < 56 * XH_STRIDE; i += 256) ((float*)s_xh)[i] = 0.f;
        __syncthreads();

        for (int t = 0; t < TT; ++t) {
            const int hco = 32 + ((t & 1) << 5);   // current h
            const int hwo = 96 - hco;              // next h

            // ---------- S1: load x + embeddings into s_in ----------
            {
                const long bt = (long)b * TT + t;
                const float* xa = X_aqi + bt * (NAq * 6);
                for (int i = tid; i < NAq * 6; i += 256) s_in[i / 6][i % 6] = xa[i];
                const float* xm = X_meo + bt * (NMe * 4);
                for (int i = tid; i < NMe * 4; i += 256) s_in[NAq + i / 4][i % 4] = xm[i];
                const int* ia = Xae + bt * (NAq * 4);
                for (int i = tid; i < NAq * 4; i += 256) {
                    int n = i >> 2, e = i & 3;
                    int idx = ia[i];
                    int off = (e == 0) ? 0 : (e == 1) ? 70 : (e == 2) ? 96 : 110;
                    s_in[n][6 + 2*e]     = s_emb[off + idx * 2];
                    s_in[n][6 + 2*e + 1] = s_emb[off + idx * 2 + 1];
                }
                const int* im = Xme + bt * (NMe * 5);
                for (int i = tid; i < NMe * 5; i += 256) {
                    int n = i / 5, e = i % 5;
                    int idx = im[i];
                    int off = (e == 0) ? 158 : (e == 1) ? 176 : (e == 2) ? 212 : (e == 3) ? 238 : 252;
                    s_in[NAq + n][4 + 2*e]     = s_emb[off + idx * 2];
                    s_in[NAq + n][4 + 2*e + 1] = s_emb[off + idx * 2 + 1];
                }
            }
            __syncthreads();   // B1

            // ---------- S2: feat + attri + src/dst (warp per node) ----------
            for (int nr = wid; nr < NN; nr += 8) {
                bool A = nr < NAq;
                float inv = (lane < 14) ? s_in[nr][lane] : 0.f;
                float f = 0.f, at = 0.f;
                if (A) {
                    #pragma unroll
                    for (int j = 0; j < 14; ++j) {
                        float xj = __shfl_sync(0xffffffffu, inv, j);
                        f = fmaf(xj, s_Wua[j * 32 + lane], f);
                        if (j < 6) at = fmaf(xj, s_Wxa[j * 32 + lane], at);
                    }
                } else {
                    #pragma unroll
                    for (int j = 0; j < 14; ++j) {
                        float xj = __shfl_sync(0xffffffffu, inv, j);
                        f = fmaf(xj, s_Wum[j * 32 + lane], f);
                        if (j < 4) at = fmaf(xj, s_Wxm[j * 32 + lane], at);
                    }
                }
                s_xh[PROW(nr)][lane] = f;
                s_attri[nr][lane] = at;
                int v0 = A ? 0 : 2, v1 = A ? 1 : 3, v2 = A ? 0 : 1, v3 = A ? 2 : 3;
                float p0 = f * s_as[v0][lane];
                float p1 = f * s_as[v1][lane];
                float p2 = f * s_ad[v2][lane];
                float p3 = f * s_ad[v3][lane];
                #pragma unroll
                for (int o = 16; o; o >>= 1) {
                    p0 += __shfl_xor_sync(0xffffffffu, p0, o);
                    p1 += __shfl_xor_sync(0xffffffffu, p1, o);
                    p2 += __shfl_xor_sync(0xffffffffu, p2, o);
                    p3 += __shfl_xor_sync(0xffffffffu, p3, o);
                }
                if (lane == 0) {
                    s_sd[0][nr] = p0 + s_ctxs[v0][nr];
                    s_sd[1][nr] = p1 + s_ctxs[v1][nr];
                    s_sd[2][nr] = p2 + s_ctxd[v2][nr];
                    s_sd[3][nr] = p3 + s_ctxd[v3][nr];
                }
            }
            __syncthreads();   // B2

            // ---------- S3: e + masked softmax (warp per row) ----------
            for (int i = wid; i < NN; i += 8) {
                bool rtA = i < NAq;
                unsigned m0 = s_mask[i][0], m1 = s_mask[i][1];
                float srcA = s_sd[0][i], srcM = s_sd[1][i];
                const float* anc = s_anc + i * NN;
                float e1, e2;
                {
                    int j = lane;
                    float v = (j < NAq ? srcA : srcM)
                            + (rtA ? s_sd[2][j] : s_sd[3][j])
                            + anc[j];
                    v = (v >= 0.f) ? v : 0.2f * v;
                    if (!((m0 >> j) & 1u)) v = -1e12f;
                    e1 = v;
                }
                {
                    int j = lane + 32;
                    if (j < NN) {
                        float v = (j < NAq ? srcA : srcM)
                                + (rtA ? s_sd[2][j] : s_sd[3][j])
                                + anc[j];
                        v = (v >= 0.f) ? v : 0.2f * v;
                        if (!((m1 >> (j - 32)) & 1u)) v = -1e12f;
                        e2 = v;
                    } else {
                        e2 = -3e38f;
                    }
                }
                float m = fmaxf(e1, e2);
                #pragma unroll
                for (int o = 16; o; o >>= 1) m = fmaxf(m, __shfl_xor_sync(0xffffffffu, m, o));
                float p1 = __expf(e1 - m);
                float p2 = (lane + 32 < NN) ? __expf(e2 - m) : 0.f;
                float s = p1 + p2;
                #pragma unroll
                for (int o = 16; o; o >>= 1) s += __shfl_xor_sync(0xffffffffu, s, o);
                float inv = 1.f / s;
                s_e[i * NN + lane] = p1 * inv;
                if (lane + 32 < NN) s_e[i * NN + lane + 32] = p2 * inv;
            }
            __syncthreads();   // B3

            // ---------- S4: att @ attri -> s_xh x slot (2 rows x f32x2) ----------
            if (tid < 216) {
                bool has1 = (a_r1 < NN);
                const float* e0 = s_e + a_r0 * NN;
                const float* e1 = s_e + (has1 ? a_r1 : a_r0) * NN;
                ull a00 = 0, a01 = 0, a10 = 0, a11 = 0;
                for (int j = 0; j < NN; ++j) {
                    longlong2 lv = *(const longlong2*)&s_attri[j][a_hq * 4];
                    ull av0 = bcast2(e0[j]);
                    ull av1 = bcast2(e1[j]);
                    fma2(a00, av0, (ull)lv.x); fma2(a01, av0, (ull)lv.y);
                    fma2(a10, av1, (ull)lv.x); fma2(a11, av1, (ull)lv.y);
                }
                *(longlong2*)&s_xh[PROW(a_r0)][a_hq * 4] =
                    make_longlong2((long long)a00, (long long)a01);
                if (has1)
                    *(longlong2*)&s_xh[PROW(a_r1)][a_hq * 4] =
                        make_longlong2((long long)a10, (long long)a11);
            }
            __syncthreads();   // B4

            // ---------- S5: GRU (double-buffered h, no internal barrier) ----------
            if (tid < 216) {
                ull ar[2][2] = {{0ull,0ull},{0ull,0ull}};
                ull az[2][2] = {{0ull,0ull},{0ull,0ull}};
                ull ai[2][2] = {{0ull,0ull},{0ull,0ull}};
                ull ah[2][2] = {{0ull,0ull},{0ull,0ull}};
                #pragma unroll
                for (int kq = 0; kq < 8; ++kq) {
                    float4 x0 = *(const float4*)&s_xh[g_p0][4 * kq];
                    float4 x1 = *(const float4*)&s_xh[g_p1][4 * kq];
                    float4 h0 = *(const float4*)&s_xh[g_p0][hco + 4 * kq];
                    float4 h1 = *(const float4*)&s_xh[g_p1][hco + 4 * kq];
                    const float xs0[4] = {x0.x, x0.y, x0.z, x0.w};
                    const float xs1[4] = {x1.x, x1.y, x1.z, x1.w};
                    const float hs0[4] = {h0.x, h0.y, h0.z, h0.w};
                    const float hs1[4] = {h1.x, h1.y, h1.z, h1.w};
                    #pragma unroll
                    for (int i = 0; i < 4; ++i) {
                        int k = kq * 4 + i;
                        const longlong2* wk = g_w2 + k * 8;
                        longlong2 wrx = __ldg(wk);
                        longlong2 wrh = __ldg(wk + 256);
                        longlong2 wzx = __ldg(wk + 512);
                        longlong2 wzh = __ldg(wk + 768);
                        longlong2 wnx = __ldg(wk + 1024);
                        longlong2 wnh = __ldg(wk + 1280);
                        ull xp0 = bcast2(xs0[i]), xp1 = bcast2(xs1[i]);
                        ull hp0 = bcast2(hs0[i]), hp1 = bcast2(hs1[i]);
                        fma2(ar[0][0], xp0, (ull)wrx.x); fma2(ar[0][1], xp0, (ull)wrx.y);
                        fma2(ar[1][0], xp1, (ull)wrx.x); fma2(ar[1][1], xp1, (ull)wrx.y);
                        fma2(ar[0][0], hp0, (ull)wrh.x); fma2(ar[0][1], hp0, (ull)wrh.y);
                        fma2(ar[1][0], hp1, (ull)wrh.x); fma2(ar[1][1], hp1, (ull)wrh.y);
                        fma2(az[0][0], xp0, (ull)wzx.x); fma2(az[0][1], xp0, (ull)wzx.y);
                        fma2(az[1][0], xp1, (ull)wzx.x); fma2(az[1][1], xp1, (ull)wzx.y);
                        fma2(az[0][0], hp0, (ull)wzh.x); fma2(az[0][1], hp0, (ull)wzh.y);
                        fma2(az[1][0], hp1, (ull)wzh.x); fma2(az[1][1], hp1, (ull)wzh.y);
                        fma2(ai[0][0], xp0, (ull)wnx.x); fma2(ai[0][1], xp0, (ull)wnx.y);
                        fma2(ai[1][0], xp1, (ull)wnx.x); fma2(ai[1][1], xp1, (ull)wnx.y);
                        fma2(ah[0][0], hp0, (ull)wnh.x); fma2(ah[0][1], hp0, (ull)wnh.y);
                        fma2(ah[1][0], hp1, (ull)wnh.x); fma2(ah[1][1], hp1, (ull)wnh.y);
                    }
                }
                int c0 = g_cq * 4;
                float rr0[4], rr1[4], zz0[4], zz1[4], ii0[4], ii1[4], hh0[4], hh1[4];
                unpack2(ar[0][0], rr0[0], rr0[1]); unpack2(ar[0][1], rr0[2], rr0[3]);
                unpack2(ar[1][0], rr1[0], rr1[1]); unpack2(ar[1][1], rr1[2], rr1[3]);
                unpack2(az[0][0], zz0[0], zz0[1]); unpack2(az[0][1], zz0[2], zz0[3]);
                unpack2(az[1][0], zz1[0], zz1[1]); unpack2(az[1][1], zz1[2], zz1[3]);
                unpack2(ai[0][0], ii0[0], ii0[1]); unpack2(ai[0][1], ii0[2], ii0[3]);
                unpack2(ai[1][0], ii1[0], ii1[1]); unpack2(ai[1][1], ii1[2], ii1[3]);
                unpack2(ah[0][0], hh0[0], hh0[1]); unpack2(ah[0][1], hh0[2], hh0[3]);
                unpack2(ah[1][0], hh1[0], hh1[1]); unpack2(ah[1][1], hh1[2], hh1[3]);
                #pragma unroll
                for (int cc = 0; cc < 4; ++cc) {
                    int c = c0 + cc;
                    float brz_r = s_brz[g_ty][c], brz_z = s_brz[g_ty][32 + c];
                    float bni = s_bni[g_ty][c], bnh = s_bnh[g_ty][c];
                    {
                        float hold = s_xh[g_p0][hco + c];
                        float r = sigf(rr0[cc] + brz_r);
                        float z = sigf(zz0[cc] + brz_z);
                        float ng = tanh_fast(ii0[cc] + bni + r * (hh0[cc] + bnh));
                        s_xh[g_p0][hwo + c] = ng + z * (hold - ng);
                    }
                    {
                        float hold = s_xh[g_p1][hco + c];
                        float r = sigf(rr1[cc] + brz_r);
                        float z = sigf(zz1[cc] + brz_z);
                        float ng = tanh_fast(ii1[cc] + bni + r * (hh1[cc] + bnh));
                        s_xh[g_p1][hwo + c] = ng + z * (hold - ng);
                    }
                }
            }
            // no barrier: next-step S1 touches only s_in; B1 orders everything else
        }  // t loop

        __syncthreads();  // GRU writes complete before reading final h (at offset 32)

        for (int item = tid; item < NN * 32; item += 256) {
            int n = item >> 5, k = item & 31;
            float v = s_xh[PROW(n)][32 + k];
            if (n < NAq)
                out[((long)b * NAq + n) * 32 + k] = v;
            else
                out[(long)B * NAq * 32 + ((long)b * NMe + (n - NAq)) * 32 + k] = v;
        }
        __syncthreads();
    }  // b loop
}

extern "C" void kernel_launch(void* const* d_in, const int* in_sizes, int n_in,
                              void* d_out, int out_size) {
    const float* X_aqi  = (const float*)d_in[0];
    const float* X_meo  = (const float*)d_in[1];
    const float* ctxf   = (const float*)d_in[2];
    const float* adj    = (const float*)d_in[3];
    const float* adjn   = (const float*)d_in[4];
    const float* e_aid  = (const float*)d_in[5];
    const float* e_amo  = (const float*)d_in[6];
    const float* e_awd  = (const float*)d_in[7];
    const float* e_ahr  = (const float*)d_in[8];
    const float* e_mwi  = (const float*)d_in[9];
    const float* e_mid  = (const float*)d_in[10];
    const float* e_mmo  = (const float*)d_in[11];
    const float* e_mwd  = (const float*)d_in[12];
    const float* e_mhr  = (const float*)d_in[13];
    const float* W_xa   = (const float*)d_in[14];
    const float* W_xm   = (const float*)d_in[15];
    const float* W_ua   = (const float*)d_in[16];
    const float* W_um   = (const float*)d_in[17];
    const float* a_aa   = (const float*)d_in[18];
    const float* a_am   = (const float*)d_in[19];
    const float* a_ma   = (const float*)d_in[20];
    const float* a_mm   = (const float*)d_in[21];
    const float* wih_a  = (const float*)d_in[22];
    const float* whh_a  = (const float*)d_in[23];
    const float* bih_a  = (const float*)d_in[24];
    const float* bhh_a  = (const float*)d_in[25];
    const float* wih_m  = (const float*)d_in[26];
    const float* whh_m  = (const float*)d_in[27];
    const float* bih_m  = (const float*)d_in[28];
    const float* bhh_m  = (const float*)d_in[29];
    const int*   Xae    = (const int*)d_in[30];
    const int*   Xme    = (const int*)d_in[31];
    float* out = (float*)d_out;

    int B = in_sizes[0] / (TT * NAq * 6);
    int grid = (B >= 512) ? 512 : B;
    size_t dynBytes = DYN_FLOATS * sizeof(float);

    cudaFuncSetAttribute(chgat_gru_kernel,
                         cudaFuncAttributeMaxDynamicSharedMemorySize, (int)dynBytes);

    prep_weights<<<48, 256>>>(wih_a, whh_a, wih_m, whh_m);
    chgat_gru_kernel<<<grid, 256, dynBytes>>>(
        X_aqi, X_meo, ctxf, adj, adjn,
        e_aid, e_amo, e_awd, e_ahr, e_mwi, e_mid, e_mmo, e_mwd, e_mhr,
        W_xa, W_xm, W_ua, W_um, a_aa, a_am, a_ma, a_mm,
        bih_a, bhh_a, bih_m, bhh_m,
        Xae, Xme, out, B);
}

// round 8
// speedup vs baseline: 1.8949x; 1.8949x over previous
#include <cuda_runtime.h>

static __device__ __forceinline__ float sigf(float x) {
    return 1.f / (1.f + __expf(-x));
}
static __device__ __forceinline__ float tanh_fast(float x) {
    return 1.f - 2.f / (__expf(2.f * x) + 1.f);
}

typedef unsigned long long ull;
static __device__ __forceinline__ void fma2(ull& d, ull a, ull b) {
    asm("fma.rn.f32x2 %0, %1, %2, %0;" : "+l"(d) : "l"(a), "l"(b));
}
static __device__ __forceinline__ ull bcast2(float x) {
    ull r;
    asm("mov.b64 %0, {%1, %1};" : "=l"(r) : "r"(__float_as_uint(x)));
    return r;
}
static __device__ __forceinline__ void unpack2(ull v, float& lo, float& hi) {
    unsigned a, b;
    asm("mov.b64 {%0, %1}, %2;" : "=r"(a), "=r"(b) : "l"(v));
    lo = __uint_as_float(a); hi = __uint_as_float(b);
}

#define TT 48
#define NAq 35
#define NMe 18
#define NN 53
#define PROW(n) ((n) + ((n) >= NAq ? 1 : 0))
#define XH_STRIDE 68

// Transposed GRU weights: [ty][mat(6)][k(32)][c(32)]
__device__ float g_wT[2 * 6 * 32 * 32];

__global__ void prep_weights(const float* __restrict__ wih_a, const float* __restrict__ whh_a,
                             const float* __restrict__ wih_m, const float* __restrict__ whh_m) {
    int i = blockIdx.x * 256 + threadIdx.x;
    if (i < 12288) {
        int c = i & 31;
        int k = (i >> 5) & 31;
        int m = (i >> 10) % 6;
        int ty = i / 6144;
        const float* W = (m & 1) ? (ty ? whh_m : whh_a) : (ty ? wih_m : wih_a);
        int gate = m >> 1;
        g_wT[i] = W[(gate * 32 + c) * 32 + k];
    }
}

__global__ __launch_bounds__(256, 3)
void chgat_gru_kernel(
    const float* __restrict__ X_aqi, const float* __restrict__ X_meo,
    const float* __restrict__ ctxf,  const float* __restrict__ adj,
    const float* __restrict__ adjn,
    const float* __restrict__ e_aid, const float* __restrict__ e_amo,
    const float* __restrict__ e_awd, const float* __restrict__ e_ahr,
    const float* __restrict__ e_mwi, const float* __restrict__ e_mid,
    const float* __restrict__ e_mmo, const float* __restrict__ e_mwd,
    const float* __restrict__ e_mhr,
    const float* __restrict__ W_xa,  const float* __restrict__ W_xm,
    const float* __restrict__ W_ua,  const float* __restrict__ W_um,
    const float* __restrict__ a_aa,  const float* __restrict__ a_am,
    const float* __restrict__ a_ma,  const float* __restrict__ a_mm,
    const float* __restrict__ bih_a, const float* __restrict__ bhh_a,
    const float* __restrict__ bih_m, const float* __restrict__ bhh_m,
    const int*   __restrict__ Xae,   const int*   __restrict__ Xme,
    float* __restrict__ out, int B)
{
    __shared__ float s_xh[56][XH_STRIDE];
    __shared__ float s_attri[NN][36];
    __shared__ float s_e[NN * NN];
    __shared__ float s_in[NN][14];
    __shared__ float s_sd[4][NN];
    __shared__ float s_ctxs[4][NN];
    __shared__ float s_ctxd[4][NN];
    __shared__ float s_as[4][32];
    __shared__ float s_ad[4][32];
    __shared__ float s_c[4];
    __shared__ unsigned s_mask[NN][2];
    __shared__ float s_brz[2][64];
    __shared__ float s_bni[2][32];
    __shared__ float s_bnh[2][32];
    __shared__ float s_Wua[14*32], s_Wum[14*32], s_Wxa[6*32], s_Wxm[4*32];
    __shared__ float s_emb[300];

    const int tid = threadIdx.x;

    // ---------------- one-time per-block init ----------------
    for (int i = tid; i < 14*32; i += 256) { s_Wua[i] = W_ua[i]; s_Wum[i] = W_um[i]; }
    for (int i = tid; i < 6*32;  i += 256) s_Wxa[i] = W_xa[i];
    for (int i = tid; i < 4*32;  i += 256) s_Wxm[i] = W_xm[i];
    for (int i = tid; i < 64; i += 256) {
        s_brz[0][i] = bih_a[i] + bhh_a[i];
        s_brz[1][i] = bih_m[i] + bhh_m[i];
    }
    for (int i = tid; i < 32; i += 256) {
        s_bni[0][i] = bih_a[64 + i]; s_bnh[0][i] = bhh_a[64 + i];
        s_bni[1][i] = bih_m[64 + i]; s_bnh[1][i] = bhh_m[64 + i];
    }
    for (int i = tid; i < 70; i += 256) s_emb[i]       = e_aid[i];
    for (int i = tid; i < 26; i += 256) s_emb[70 + i]  = e_amo[i];
    for (int i = tid; i < 14; i += 256) s_emb[96 + i]  = e_awd[i];
    for (int i = tid; i < 48; i += 256) s_emb[110 + i] = e_ahr[i];
    for (int i = tid; i < 18; i += 256) s_emb[158 + i] = e_mwi[i];
    for (int i = tid; i < 36; i += 256) s_emb[176 + i] = e_mid[i];
    for (int i = tid; i < 26; i += 256) s_emb[212 + i] = e_mmo[i];
    for (int i = tid; i < 14; i += 256) s_emb[238 + i] = e_mwd[i];
    for (int i = tid; i < 48; i += 256) s_emb[252 + i] = e_mhr[i];
    for (int i = tid; i < 128; i += 256) {
        int v = i >> 5, j = i & 31;
        const float* av = (v == 0) ? a_aa : (v == 1) ? a_am : (v == 2) ? a_ma : a_mm;
        s_as[v][j] = av[j];
        s_ad[v][j] = av[92 + j];
    }
    if (tid < 4) {
        const float* av = (tid == 0) ? a_aa : (tid == 1) ? a_am : (tid == 2) ? a_ma : a_mm;
        s_c[tid] = av[184];
    }
    if (tid < NN) {
        unsigned m0 = 0, m1 = 0;
        for (int j = 0; j < 32; ++j)  if (adj[tid * NN + j] > 0.f) m0 |= (1u << j);
        for (int j = 32; j < NN; ++j) if (adj[tid * NN + j] > 0.f) m1 |= (1u << (j - 32));
        s_mask[tid][0] = m0; s_mask[tid][1] = m1;
    }
    for (int item = tid; item < 4 * NN; item += 256) {
        int v = item / NN, n = item % NN;
        const float* av = (v == 0) ? a_aa : (v == 1) ? a_am : (v == 2) ? a_ma : a_mm;
        float s1 = 0.f, s2 = 0.f;
        for (int c = 0; c < 60; ++c) {
            float cv = ctxf[n * 60 + c];
            s1 = fmaf(cv, av[32 + c], s1);
            s2 = fmaf(cv, av[124 + c], s2);
        }
        s_ctxs[v][n] = s1; s_ctxd[v][n] = s2;
    }
    __syncthreads();

    const int wid = tid >> 5, lane = tid & 31;
    // GRU tile coords (tid < 216): 27 row-pairs x 8 col-quads
    const int g_rt = tid >> 3, g_cq = tid & 7;
    const int g_p0 = 2 * g_rt, g_p1 = 2 * g_rt + 1;
    const int g_ty = (g_rt < 18) ? 0 : 1;
    const longlong2* g_w2 = (const longlong2*)g_wT + g_ty * 1536 + g_cq;
    // att tile coords (tid < 216): 27 row-pairs x 8 col-quads
    const int a_p = tid >> 3, a_hq = tid & 7;
    const int a_r0 = a_p, a_r1 = a_p + 27;

    for (int b = blockIdx.x; b < B; b += gridDim.x) {
        for (int i = tid; i < 56 * XH_STRIDE; i += 256) ((float*)s_xh)[i] = 0.f;
        __syncthreads();

        for (int t = 0; t < TT; ++t) {
            // ---------- S1: load x + embeddings into s_in ----------
            {
                const long bt = (long)b * TT + t;
                const float* xa = X_aqi + bt * (NAq * 6);
                for (int i = tid; i < NAq * 6; i += 256) s_in[i / 6][i % 6] = xa[i];
                const float* xm = X_meo + bt * (NMe * 4);
                for (int i = tid; i < NMe * 4; i += 256) s_in[NAq + i / 4][i % 4] = xm[i];
                const int* ia = Xae + bt * (NAq * 4);
                for (int i = tid; i < NAq * 4; i += 256) {
                    int n = i >> 2, e = i & 3;
                    int idx = ia[i];
                    int off = (e == 0) ? 0 : (e == 1) ? 70 : (e == 2) ? 96 : 110;
                    s_in[n][6 + 2*e]     = s_emb[off + idx * 2];
                    s_in[n][6 + 2*e + 1] = s_emb[off + idx * 2 + 1];
                }
                const int* im = Xme + bt * (NMe * 5);
                for (int i = tid; i < NMe * 5; i += 256) {
                    int n = i / 5, e = i % 5;
                    int idx = im[i];
                    int off = (e == 0) ? 158 : (e == 1) ? 176 : (e == 2) ? 212 : (e == 3) ? 238 : 252;
                    s_in[NAq + n][4 + 2*e]     = s_emb[off + idx * 2];
                    s_in[NAq + n][4 + 2*e + 1] = s_emb[off + idx * 2 + 1];
                }
            }
            __syncthreads();

            // ---------- S2: feat (learned part -> s_xh x slot) + attri ----------
            for (int item = tid; item < NN * 32; item += 256) {
                int n = item >> 5, h = item & 31;
                const float* in = s_in[n];
                float f = 0.f, at = 0.f;
                if (n < NAq) {
                    #pragma unroll
                    for (int j = 0; j < 14; ++j) f = fmaf(in[j], s_Wua[j * 32 + h], f);
                    #pragma unroll
                    for (int j = 0; j < 6; ++j)  at = fmaf(in[j], s_Wxa[j * 32 + h], at);
                } else {
                    #pragma unroll
                    for (int j = 0; j < 14; ++j) f = fmaf(in[j], s_Wum[j * 32 + h], f);
                    #pragma unroll
                    for (int j = 0; j < 4; ++j)  at = fmaf(in[j], s_Wxm[j * 32 + h], at);
                }
                s_xh[PROW(n)][h] = f;
                s_attri[n][h] = at;
            }
            __syncthreads();

            // ---------- S3: src/dst projections ----------
            for (int item = tid; item < 4 * NN; item += 256) {
                int v = item / NN, n = item % NN;
                bool A = n < NAq;
                int vid = (v == 0) ? (A ? 0 : 2)
                        : (v == 1) ? (A ? 1 : 3)
                        : (v == 2) ? (A ? 0 : 1)
                                   : (A ? 2 : 3);
                const float* w = (v < 2) ? s_as[vid] : s_ad[vid];
                float acc = (v < 2) ? s_ctxs[vid][n] : s_ctxd[vid][n];
                const float* fr = s_xh[PROW(n)];
                #pragma unroll
                for (int j = 0; j < 32; ++j) acc = fmaf(fr[j], w[j], acc);
                s_sd[v][n] = acc;
            }
            __syncthreads();

            // ---------- S4: e + masked softmax (fused, warp per row) ----------
            for (int i = wid; i < NN; i += 8) {
                bool rtA = i < NAq;
                const float* an = adjn + i * NN;
                unsigned m0 = s_mask[i][0], m1 = s_mask[i][1];
                float srcA = s_sd[0][i], srcM = s_sd[1][i];
                float e1, e2;
                {
                    int j = lane;
                    bool ctA = j < NAq;
                    float v = (ctA ? srcA : srcM)
                            + (rtA ? s_sd[2][j] : s_sd[3][j])
                            + __ldg(an + j) * s_c[rtA ? (ctA ? 0 : 1) : (ctA ? 2 : 3)];
                    v = (v >= 0.f) ? v : 0.2f * v;
                    if (!((m0 >> j) & 1u)) v = -1e12f;
                    e1 = v;
                }
                {
                    int j = lane + 32;
                    if (j < NN) {
                        bool ctA = j < NAq;
                        float v = (ctA ? srcA : srcM)
                                + (rtA ? s_sd[2][j] : s_sd[3][j])
                                + __ldg(an + j) * s_c[rtA ? (ctA ? 0 : 1) : (ctA ? 2 : 3)];
                        v = (v >= 0.f) ? v : 0.2f * v;
                        if (!((m1 >> (j - 32)) & 1u)) v = -1e12f;
                        e2 = v;
                    } else {
                        e2 = -3e38f;
                    }
                }
                float m = fmaxf(e1, e2);
                #pragma unroll
                for (int o = 16; o; o >>= 1) m = fmaxf(m, __shfl_xor_sync(0xffffffffu, m, o));
                float p1 = __expf(e1 - m);
                float p2 = (lane + 32 < NN) ? __expf(e2 - m) : 0.f;
                float s = p1 + p2;
                #pragma unroll
                for (int o = 16; o; o >>= 1) s += __shfl_xor_sync(0xffffffffu, s, o);
                float inv = 1.f / s;
                s_e[i * NN + lane] = p1 * inv;
                if (lane + 32 < NN) s_e[i * NN + lane + 32] = p2 * inv;
            }
            __syncthreads();

            // ---------- S5: att @ attri -> s_xh x slot (2 rows x f32x2) ----------
            if (tid < 216) {
                bool has1 = (a_r1 < NN);
                const float* e0 = s_e + a_r0 * NN;
                const float* e1 = s_e + (has1 ? a_r1 : a_r0) * NN;
                ull a00 = 0, a01 = 0, a10 = 0, a11 = 0;
                #pragma unroll 4
                for (int j = 0; j < NN; ++j) {
                    longlong2 lv = *(const longlong2*)&s_attri[j][a_hq * 4];
                    ull av0 = bcast2(e0[j]);
                    ull av1 = bcast2(e1[j]);
                    fma2(a00, av0, (ull)lv.x); fma2(a01, av0, (ull)lv.y);
                    fma2(a10, av1, (ull)lv.x); fma2(a11, av1, (ull)lv.y);
                }
                *(longlong2*)&s_xh[PROW(a_r0)][a_hq * 4] =
                    make_longlong2((long long)a00, (long long)a01);
                if (has1)
                    *(longlong2*)&s_xh[PROW(a_r1)][a_hq * 4] =
                        make_longlong2((long long)a10, (long long)a11);
            }
            __syncthreads();

            // ---------- S6: GRU (register-tiled, 2 rows x 4 cols, f32x2) ----------
            ull ar[2][2] = {{0ull,0ull},{0ull,0ull}};
            ull az[2][2] = {{0ull,0ull},{0ull,0ull}};
            ull ai[2][2] = {{0ull,0ull},{0ull,0ull}};
            ull ah[2][2] = {{0ull,0ull},{0ull,0ull}};
            float hold0[4], hold1[4];
            if (tid < 216) {
                #pragma unroll
                for (int kq = 0; kq < 8; ++kq) {
                    float4 x0 = *(const float4*)&s_xh[g_p0][4 * kq];
                    float4 x1 = *(const float4*)&s_xh[g_p1][4 * kq];
                    float4 h0 = *(const float4*)&s_xh[g_p0][32 + 4 * kq];
                    float4 h1 = *(const float4*)&s_xh[g_p1][32 + 4 * kq];
                    const float xs0[4] = {x0.x, x0.y, x0.z, x0.w};
                    const float xs1[4] = {x1.x, x1.y, x1.z, x1.w};
                    const float hs0[4] = {h0.x, h0.y, h0.z, h0.w};
                    const float hs1[4] = {h1.x, h1.y, h1.z, h1.w};
                    #pragma unroll
                    for (int i = 0; i < 4; ++i) {
                        int k = kq * 4 + i;
                        const longlong2* wk = g_w2 + k * 8;
                        longlong2 wrx = __ldg(wk);
                        longlong2 wrh = __ldg(wk + 256);
                        longlong2 wzx = __ldg(wk + 512);
                        longlong2 wzh = __ldg(wk + 768);
                        longlong2 wnx = __ldg(wk + 1024);
                        longlong2 wnh = __ldg(wk + 1280);
                        ull xp0 = bcast2(xs0[i]), xp1 = bcast2(xs1[i]);
                        ull hp0 = bcast2(hs0[i]), hp1 = bcast2(hs1[i]);
                        fma2(ar[0][0], xp0, (ull)wrx.x); fma2(ar[0][1], xp0, (ull)wrx.y);
                        fma2(ar[1][0], xp1, (ull)wrx.x); fma2(ar[1][1], xp1, (ull)wrx.y);
                        fma2(ar[0][0], hp0, (ull)wrh.x); fma2(ar[0][1], hp0, (ull)wrh.y);
                        fma2(ar[1][0], hp1, (ull)wrh.x); fma2(ar[1][1], hp1, (ull)wrh.y);
                        fma2(az[0][0], xp0, (ull)wzx.x); fma2(az[0][1], xp0, (ull)wzx.y);
                        fma2(az[1][0], xp1, (ull)wzx.x); fma2(az[1][1], xp1, (ull)wzx.y);
                        fma2(az[0][0], hp0, (ull)wzh.x); fma2(az[0][1], hp0, (ull)wzh.y);
                        fma2(az[1][0], hp1, (ull)wzh.x); fma2(az[1][1], hp1, (ull)wzh.y);
                        fma2(ai[0][0], xp0, (ull)wnx.x); fma2(ai[0][1], xp0, (ull)wnx.y);
                        fma2(ai[1][0], xp1, (ull)wnx.x); fma2(ai[1][1], xp1, (ull)wnx.y);
                        fma2(ah[0][0], hp0, (ull)wnh.x); fma2(ah[0][1], hp0, (ull)wnh.y);
                        fma2(ah[1][0], hp1, (ull)wnh.x); fma2(ah[1][1], hp1, (ull)wnh.y);
                    }
                }
                int c0 = g_cq * 4;
                #pragma unroll
                for (int cc = 0; cc < 4; ++cc) {
                    hold0[cc] = s_xh[g_p0][32 + c0 + cc];
                    hold1[cc] = s_xh[g_p1][32 + c0 + cc];
                }
            }
            __syncthreads();
            if (tid < 216) {
                int c0 = g_cq * 4;
                float rr0[4], rr1[4], zz0[4], zz1[4], ii0[4], ii1[4], hh0[4], hh1[4];
                unpack2(ar[0][0], rr0[0], rr0[1]); unpack2(ar[0][1], rr0[2], rr0[3]);
                unpack2(ar[1][0], rr1[0], rr1[1]); unpack2(ar[1][1], rr1[2], rr1[3]);
                unpack2(az[0][0], zz0[0], zz0[1]); unpack2(az[0][1], zz0[2], zz0[3]);
                unpack2(az[1][0], zz1[0], zz1[1]); unpack2(az[1][1], zz1[2], zz1[3]);
                unpack2(ai[0][0], ii0[0], ii0[1]); unpack2(ai[0][1], ii0[2], ii0[3]);
                unpack2(ai[1][0], ii1[0], ii1[1]); unpack2(ai[1][1], ii1[2], ii1[3]);
                unpack2(ah[0][0], hh0[0], hh0[1]); unpack2(ah[0][1], hh0[2], hh0[3]);
                unpack2(ah[1][0], hh1[0], hh1[1]); unpack2(ah[1][1], hh1[2], hh1[3]);
                #pragma unroll
                for (int cc = 0; cc < 4; ++cc) {
                    int c = c0 + cc;
                    float brz_r = s_brz[g_ty][c], brz_z = s_brz[g_ty][32 + c];
                    float bni = s_bni[g_ty][c], bnh = s_bnh[g_ty][c];
                    {
                        float r = sigf(rr0[cc] + brz_r);
                        float z = sigf(zz0[cc] + brz_z);
                        float ng = tanh_fast(ii0[cc] + bni + r * (hh0[cc] + bnh));
                        s_xh[g_p0][32 + c] = ng + z * (hold0[cc] - ng);
                    }
                    {
                        float r = sigf(rr1[cc] + brz_r);
                        float z = sigf(zz1[cc] + brz_z);
                        float ng = tanh_fast(ii1[cc] + bni + r * (hh1[cc] + bnh));
                        s_xh[g_p1][32 + c] = ng + z * (hold1[cc] - ng);
                    }
                }
            }
            __syncthreads();
        }  // t loop

        // ---------- write final hidden state ----------
        for (int item = tid; item < NN * 32; item += 256) {
            int n = item >> 5, k = item & 31;
            float v = s_xh[PROW(n)][32 + k];
            if (n < NAq)
                out[((long)b * NAq + n) * 32 + k] = v;
            else
                out[(long)B * NAq * 32 + ((long)b * NMe + (n - NAq)) * 32 + k] = v;
        }
        __syncthreads();
    }  // b loop
}

extern "C" void kernel_launch(void* const* d_in, const int* in_sizes, int n_in,
                              void* d_out, int out_size) {
    const float* X_aqi  = (const float*)d_in[0];
    const float* X_meo  = (const float*)d_in[1];
    const float* ctxf   = (const float*)d_in[2];
    const float* adj    = (const float*)d_in[3];
    const float* adjn   = (const float*)d_in[4];
    const float* e_aid  = (const float*)d_in[5];
    const float* e_amo  = (const float*)d_in[6];
    const float* e_awd  = (const float*)d_in[7];
    const float* e_ahr  = (const float*)d_in[8];
    const float* e_mwi  = (const float*)d_in[9];
    const float* e_mid  = (const float*)d_in[10];
    const float* e_mmo  = (const float*)d_in[11];
    const float* e_mwd  = (const float*)d_in[12];
    const float* e_mhr  = (const float*)d_in[13];
    const float* W_xa   = (const float*)d_in[14];
    const float* W_xm   = (const float*)d_in[15];
    const float* W_ua   = (const float*)d_in[16];
    const float* W_um   = (const float*)d_in[17];
    const float* a_aa   = (const float*)d_in[18];
    const float* a_am   = (const float*)d_in[19];
    const float* a_ma   = (const float*)d_in[20];
    const float* a_mm   = (const float*)d_in[21];
    const float* wih_a  = (const float*)d_in[22];
    const float* whh_a  = (const float*)d_in[23];
    const float* bih_a  = (const float*)d_in[24];
    const float* bhh_a  = (const float*)d_in[25];
    const float* wih_m  = (const float*)d_in[26];
    const float* whh_m  = (const float*)d_in[27];
    const float* bih_m  = (const float*)d_in[28];
    const float* bhh_m  = (const float*)d_in[29];
    const int*   Xae    = (const int*)d_in[30];
    const int*   Xme    = (const int*)d_in[31];
    float* out = (float*)d_out;

    int B = in_sizes[0] / (TT * NAq * 6);
    int grid = (B >= 512) ? 512 : B;

    prep_weights<<<48, 256>>>(wih_a, whh_a, wih_m, whh_m);
    chgat_gru_kernel<<<grid, 256>>>(
        X_aqi, X_meo, ctxf, adj, adjn,
        e_aid, e_amo, e_awd, e_ahr, e_mwi, e_mid, e_mmo, e_mwd, e_mhr,
        W_xa, W_xm, W_ua, W_um, a_aa, a_am, a_ma, a_mm,
        bih_a, bhh_a, bih_m, bhh_m,
        Xae, Xme, out, B);
}

// round 11
// speedup vs baseline: 2.0453x; 1.0793x over previous
#include <cuda_runtime.h>

static __device__ __forceinline__ float sigf(float x) {
    return 1.f / (1.f + __expf(-x));
}
static __device__ __forceinline__ float tanh_fast(float x) {
    return 1.f - 2.f / (__expf(2.f * x) + 1.f);
}

typedef unsigned long long ull;
static __device__ __forceinline__ void fma2(ull& d, ull a, ull b) {
    asm("fma.rn.f32x2 %0, %1, %2, %0;" : "+l"(d) : "l"(a), "l"(b));
}
static __device__ __forceinline__ ull bcast2(float x) {
    ull r;
    asm("mov.b64 %0, {%1, %1};" : "=l"(r) : "r"(__float_as_uint(x)));
    return r;
}
static __device__ __forceinline__ void unpack2(ull v, float& lo, float& hi) {
    unsigned a, b;
    asm("mov.b64 {%0, %1}, %2;" : "=r"(a), "=r"(b) : "l"(v));
    lo = __uint_as_float(a); hi = __uint_as_float(b);
}

#define TT 48
#define NAq 35
#define NMe 18
#define NN 53
#define ESTRIDE 56
#define PROW(n) ((n) + ((n) >= NAq ? 1 : 0))
#define XH_STRIDE 68

// Transposed GRU weights: [ty][mat(6)][k(32)][c(32)]
__device__ __align__(16) float g_wT[2 * 6 * 32 * 32];

__global__ void prep_weights(const float* __restrict__ wih_a, const float* __restrict__ whh_a,
                             const float* __restrict__ wih_m, const float* __restrict__ whh_m) {
    int i = blockIdx.x * 256 + threadIdx.x;
    if (i < 12288) {
        int c = i & 31;
        int k = (i >> 5) & 31;
        int m = (i >> 10) % 6;
        int ty = i / 6144;
        const float* W = (m & 1) ? (ty ? whh_m : whh_a) : (ty ? wih_m : wih_a);
        int gate = m >> 1;
        g_wT[i] = W[(gate * 32 + c) * 32 + k];
    }
}

__global__ __launch_bounds__(256, 3)
void chgat_gru_kernel(
    const float* __restrict__ X_aqi, const float* __restrict__ X_meo,
    const float* __restrict__ ctxf,  const float* __restrict__ adj,
    const float* __restrict__ adjn,
    const float* __restrict__ e_aid, const float* __restrict__ e_amo,
    const float* __restrict__ e_awd, const float* __restrict__ e_ahr,
    const float* __restrict__ e_mwi, const float* __restrict__ e_mid,
    const float* __restrict__ e_mmo, const float* __restrict__ e_mwd,
    const float* __restrict__ e_mhr,
    const float* __restrict__ W_xa,  const float* __restrict__ W_xm,
    const float* __restrict__ W_ua,  const float* __restrict__ W_um,
    const float* __restrict__ a_aa,  const float* __restrict__ a_am,
    const float* __restrict__ a_ma,  const float* __restrict__ a_mm,
    const float* __restrict__ bih_a, const float* __restrict__ bhh_a,
    const float* __restrict__ bih_m, const float* __restrict__ bhh_m,
    const int*   __restrict__ Xae,   const int*   __restrict__ Xme,
    float* __restrict__ out, int B)
{
    __shared__ __align__(16) float s_xh[56][XH_STRIDE];
    __shared__ __align__(16) float s_attri[NN][36];
    __shared__ __align__(16) float s_e[NN * ESTRIDE];
    __shared__ float s_in[NN][14];
    __shared__ float s_sd[4][NN];
    __shared__ float s_ctxs[4][NN];
    __shared__ float s_ctxd[4][NN];
    __shared__ __align__(16) float s_as[4][32];
    __shared__ __align__(16) float s_ad[4][32];
    __shared__ float s_c[4];
    __shared__ unsigned s_mask[NN][2];
    __shared__ float s_brz[2][64];
    __shared__ float s_bni[2][32];
    __shared__ float s_bnh[2][32];
    __shared__ float s_Wua[14*32], s_Wum[14*32], s_Wxa[6*32], s_Wxm[4*32];
    __shared__ float s_emb[300];

    const int tid = threadIdx.x;

    // ---------------- one-time per-block init ----------------
    for (int i = tid; i < 14*32; i += 256) { s_Wua[i] = W_ua[i]; s_Wum[i] = W_um[i]; }
    for (int i = tid; i < 6*32;  i += 256) s_Wxa[i] = W_xa[i];
    for (int i = tid; i < 4*32;  i += 256) s_Wxm[i] = W_xm[i];
    for (int i = tid; i < 64; i += 256) {
        s_brz[0][i] = bih_a[i] + bhh_a[i];
        s_brz[1][i] = bih_m[i] + bhh_m[i];
    }
    for (int i = tid; i < 32; i += 256) {
        s_bni[0][i] = bih_a[64 + i]; s_bnh[0][i] = bhh_a[64 + i];
        s_bni[1][i] = bih_m[64 + i]; s_bnh[1][i] = bhh_m[64 + i];
    }
    for (int i = tid; i < 70; i += 256) s_emb[i]       = e_aid[i];
    for (int i = tid; i < 26; i += 256) s_emb[70 + i]  = e_amo[i];
    for (int i = tid; i < 14; i += 256) s_emb[96 + i]  = e_awd[i];
    for (int i = tid; i < 48; i += 256) s_emb[110 + i] = e_ahr[i];
    for (int i = tid; i < 18; i += 256) s_emb[158 + i] = e_mwi[i];
    for (int i = tid; i < 36; i += 256) s_emb[176 + i] = e_mid[i];
    for (int i = tid; i < 26; i += 256) s_emb[212 + i] = e_mmo[i];
    for (int i = tid; i < 14; i += 256) s_emb[238 + i] = e_mwd[i];
    for (int i = tid; i < 48; i += 256) s_emb[252 + i] = e_mhr[i];
    for (int i = tid; i < 128; i += 256) {
        int v = i >> 5, j = i & 31;
        const float* av = (v == 0) ? a_aa : (v == 1) ? a_am : (v == 2) ? a_ma : a_mm;
        s_as[v][j] = av[j];
        s_ad[v][j] = av[92 + j];
    }
    if (tid < 4) {
        const float* av = (tid == 0) ? a_aa : (tid == 1) ? a_am : (tid == 2) ? a_ma : a_mm;
        s_c[tid] = av[184];
    }
    if (tid < NN) {
        unsigned m0 = 0, m1 = 0;
        for (int j = 0; j < 32; ++j)  if (adj[tid * NN + j] > 0.f) m0 |= (1u << j);
        for (int j = 32; j < NN; ++j) if (adj[tid * NN + j] > 0.f) m1 |= (1u << (j - 32));
        s_mask[tid][0] = m0; s_mask[tid][1] = m1;
    }
    for (int item = tid; item < 4 * NN; item += 256) {
        int v = item / NN, n = item % NN;
        const float* av = (v == 0) ? a_aa : (v == 1) ? a_am : (v == 2) ? a_ma : a_mm;
        float s1 = 0.f, s2 = 0.f;
        for (int c = 0; c < 60; ++c) {
            float cv = ctxf[n * 60 + c];
            s1 = fmaf(cv, av[32 + c], s1);
            s2 = fmaf(cv, av[124 + c], s2);
        }
        s_ctxs[v][n] = s1; s_ctxd[v][n] = s2;
    }
    __syncthreads();

    const int wid = tid >> 5, lane = tid & 31;
    // GRU tile coords (tid < 216): 27 row-pairs x 8 col-quads
    const int g_rt = tid >> 3, g_cq = tid & 7;
    const int g_p0 = 2 * g_rt, g_p1 = 2 * g_rt + 1;
    const int g_ty = (g_rt < 18) ? 0 : 1;
    const longlong2* g_w2 = (const longlong2*)g_wT + g_ty * 1536 + g_cq;
    // att tile coords (tid < 216): 27 row-pairs x 8 col-quads
    const int a_p = tid >> 3, a_hq = tid & 7;
    const int a_r0 = a_p, a_r1 = a_p + 27;

    for (int b = blockIdx.x; b < B; b += gridDim.x) {
        for (int i = tid; i < 56 * XH_STRIDE; i += 256) ((float*)s_xh)[i] = 0.f;
        __syncthreads();

        for (int t = 0; t < TT; ++t) {
            // ---------- S1: load x + embeddings into s_in ----------
            {
                const long bt = (long)b * TT + t;
                const float* xa = X_aqi + bt * (NAq * 6);
                for (int i = tid; i < NAq * 6; i += 256) s_in[i / 6][i % 6] = xa[i];
                const float* xm = X_meo + bt * (NMe * 4);
                for (int i = tid; i < NMe * 4; i += 256) s_in[NAq + i / 4][i % 4] = xm[i];
                const int* ia = Xae + bt * (NAq * 4);
                for (int i = tid; i < NAq * 4; i += 256) {
                    int n = i >> 2, e = i & 3;
                    int idx = ia[i];
                    int off = (e == 0) ? 0 : (e == 1) ? 70 : (e == 2) ? 96 : 110;
                    s_in[n][6 + 2*e]     = s_emb[off + idx * 2];
                    s_in[n][6 + 2*e + 1] = s_emb[off + idx * 2 + 1];
                }
                const int* im = Xme + bt * (NMe * 5);
                for (int i = tid; i < NMe * 5; i += 256) {
                    int n = i / 5, e = i % 5;
                    int idx = im[i];
                    int off = (e == 0) ? 158 : (e == 1) ? 176 : (e == 2) ? 212 : (e == 3) ? 238 : 252;
                    s_in[NAq + n][4 + 2*e]     = s_emb[off + idx * 2];
                    s_in[NAq + n][4 + 2*e + 1] = s_emb[off + idx * 2 + 1];
                }
            }
            __syncthreads();   // B1

            // ---------- S2: feat (learned part -> s_xh x slot) + attri ----------
            for (int item = tid; item < NN * 32; item += 256) {
                int n = item >> 5, h = item & 31;
                const float* in = s_in[n];
                float f = 0.f, at = 0.f;
                if (n < NAq) {
                    #pragma unroll
                    for (int j = 0; j < 14; ++j) f = fmaf(in[j], s_Wua[j * 32 + h], f);
                    #pragma unroll
                    for (int j = 0; j < 6; ++j)  at = fmaf(in[j], s_Wxa[j * 32 + h], at);
                } else {
                    #pragma unroll
                    for (int j = 0; j < 14; ++j) f = fmaf(in[j], s_Wum[j * 32 + h], f);
                    #pragma unroll
                    for (int j = 0; j < 4; ++j)  at = fmaf(in[j], s_Wxm[j * 32 + h], at);
                }
                s_xh[PROW(n)][h] = f;
                s_attri[n][h] = at;
            }
            __syncthreads();   // B2

            // ---------- S3: src/dst projections (float4) ----------
            for (int item = tid; item < 4 * NN; item += 256) {
                int v = item / NN, n = item % NN;
                bool A = n < NAq;
                int vid = (v == 0) ? (A ? 0 : 2)
                        : (v == 1) ? (A ? 1 : 3)
                        : (v == 2) ? (A ? 0 : 1)
                                   : (A ? 2 : 3);
                const float4* w4 = (const float4*)((v < 2) ? s_as[vid] : s_ad[vid]);
                float acc = (v < 2) ? s_ctxs[vid][n] : s_ctxd[vid][n];
                const float4* fr4 = (const float4*)s_xh[PROW(n)];
                #pragma unroll
                for (int q = 0; q < 8; ++q) {
                    float4 fv = fr4[q], wv = w4[q];
                    acc = fmaf(fv.x, wv.x, acc);
                    acc = fmaf(fv.y, wv.y, acc);
                    acc = fmaf(fv.z, wv.z, acc);
                    acc = fmaf(fv.w, wv.w, acc);
                }
                s_sd[v][n] = acc;
            }
            __syncthreads();   // B3

            // ---------- S4: e + masked softmax (fused, warp per row) ----------
            for (int i = wid; i < NN; i += 8) {
                bool rtA = i < NAq;
                const float* an = adjn + i * NN;
                unsigned m0 = s_mask[i][0], m1 = s_mask[i][1];
                float srcA = s_sd[0][i], srcM = s_sd[1][i];
                float e1, e2;
                {
                    int j = lane;
                    bool ctA = j < NAq;
                    float v = (ctA ? srcA : srcM)
                            + (rtA ? s_sd[2][j] : s_sd[3][j])
                            + __ldg(an + j) * s_c[rtA ? (ctA ? 0 : 1) : (ctA ? 2 : 3)];
                    v = (v >= 0.f) ? v : 0.2f * v;
                    if (!((m0 >> j) & 1u)) v = -1e12f;
                    e1 = v;
                }
                {
                    int j = lane + 32;
                    if (j < NN) {
                        bool ctA = j < NAq;
                        float v = (ctA ? srcA : srcM)
                                + (rtA ? s_sd[2][j] : s_sd[3][j])
                                + __ldg(an + j) * s_c[rtA ? (ctA ? 0 : 1) : (ctA ? 2 : 3)];
                        v = (v >= 0.f) ? v : 0.2f * v;
                        if (!((m1 >> (j - 32)) & 1u)) v = -1e12f;
                        e2 = v;
                    } else {
                        e2 = -3e38f;
                    }
                }
                float m = fmaxf(e1, e2);
                #pragma unroll
                for (int o = 16; o; o >>= 1) m = fmaxf(m, __shfl_xor_sync(0xffffffffu, m, o));
                float p1 = __expf(e1 - m);
                float p2 = (lane + 32 < NN) ? __expf(e2 - m) : 0.f;
                float s = p1 + p2;
                #pragma unroll
                for (int o = 16; o; o >>= 1) s += __shfl_xor_sync(0xffffffffu, s, o);
                float inv = 1.f / s;
                s_e[i * ESTRIDE + lane] = p1 * inv;
                if (lane + 32 < NN) s_e[i * ESTRIDE + lane + 32] = p2 * inv;
            }
            __syncthreads();   // B4

            // ---------- S5: att @ attri -> s_xh x slot (2 rows, float4 e, f32x2) ----------
            if (tid < 216) {
                bool has1 = (a_r1 < NN);
                const float4* e0q = (const float4*)(s_e + a_r0 * ESTRIDE);
                const float4* e1q = (const float4*)(s_e + (has1 ? a_r1 : a_r0) * ESTRIDE);
                ull a00 = 0, a01 = 0, a10 = 0, a11 = 0;
                #pragma unroll 1
                for (int jq = 0; jq < 13; ++jq) {
                    float4 ev0 = e0q[jq], ev1 = e1q[jq];
                    const float es0[4] = {ev0.x, ev0.y, ev0.z, ev0.w};
                    const float es1[4] = {ev1.x, ev1.y, ev1.z, ev1.w};
                    #pragma unroll
                    for (int u = 0; u < 4; ++u) {
                        int j = jq * 4 + u;
                        longlong2 lv = *(const longlong2*)&s_attri[j][a_hq * 4];
                        ull av0 = bcast2(es0[u]);
                        ull av1 = bcast2(es1[u]);
                        fma2(a00, av0, (ull)lv.x); fma2(a01, av0, (ull)lv.y);
                        fma2(a10, av1, (ull)lv.x); fma2(a11, av1, (ull)lv.y);
                    }
                }
                {   // j = 52 remainder
                    longlong2 lv = *(const longlong2*)&s_attri[52][a_hq * 4];
                    ull av0 = bcast2(s_e[a_r0 * ESTRIDE + 52]);
                    ull av1 = bcast2(s_e[(has1 ? a_r1 : a_r0) * ESTRIDE + 52]);
                    fma2(a00, av0, (ull)lv.x); fma2(a01, av0, (ull)lv.y);
                    fma2(a10, av1, (ull)lv.x); fma2(a11, av1, (ull)lv.y);
                }
                *(longlong2*)&s_xh[PROW(a_r0)][a_hq * 4] =
                    make_longlong2((long long)a00, (long long)a01);
                if (has1)
                    *(longlong2*)&s_xh[PROW(a_r1)][a_hq * 4] =
                        make_longlong2((long long)a10, (long long)a11);
            }
            __syncthreads();   // B5

            // ---------- S6: GRU (register-tiled, 2 rows x 4 cols, f32x2) ----------
            ull ar[2][2] = {{0ull,0ull},{0ull,0ull}};
            ull az[2][2] = {{0ull,0ull},{0ull,0ull}};
            ull ai[2][2] = {{0ull,0ull},{0ull,0ull}};
            ull ah[2][2] = {{0ull,0ull},{0ull,0ull}};
            float hold0[4], hold1[4];
            if (tid < 216) {
                #pragma unroll
                for (int kq = 0; kq < 8; ++kq) {
                    float4 x0 = *(const float4*)&s_xh[g_p0][4 * kq];
                    float4 x1 = *(const float4*)&s_xh[g_p1][4 * kq];
                    float4 h0 = *(const float4*)&s_xh[g_p0][32 + 4 * kq];
                    float4 h1 = *(const float4*)&s_xh[g_p1][32 + 4 * kq];
                    const float xs0[4] = {x0.x, x0.y, x0.z, x0.w};
                    const float xs1[4] = {x1.x, x1.y, x1.z, x1.w};
                    const float hs0[4] = {h0.x, h0.y, h0.z, h0.w};
                    const float hs1[4] = {h1.x, h1.y, h1.z, h1.w};
                    #pragma unroll
                    for (int i = 0; i < 4; ++i) {
                        int k = kq * 4 + i;
                        const longlong2* wk = g_w2 + k * 8;
                        longlong2 wrx = __ldg(wk);
                        longlong2 wrh = __ldg(wk + 256);
                        longlong2 wzx = __ldg(wk + 512);
                        longlong2 wzh = __ldg(wk + 768);
                        longlong2 wnx = __ldg(wk + 1024);
                        longlong2 wnh = __ldg(wk + 1280);
                        ull xp0 = bcast2(xs0[i]), xp1 = bcast2(xs1[i]);
                        ull hp0 = bcast2(hs0[i]), hp1 = bcast2(hs1[i]);
                        fma2(ar[0][0], xp0, (ull)wrx.x); fma2(ar[0][1], xp0, (ull)wrx.y);
                        fma2(ar[1][0], xp1, (ull)wrx.x); fma2(ar[1][1], xp1, (ull)wrx.y);
                        fma2(ar[0][0], hp0, (ull)wrh.x); fma2(ar[0][1], hp0, (ull)wrh.y);
                        fma2(ar[1][0], hp1, (ull)wrh.x); fma2(ar[1][1], hp1, (ull)wrh.y);
                        fma2(az[0][0], xp0, (ull)wzx.x); fma2(az[0][1], xp0, (ull)wzx.y);
                        fma2(az[1][0], xp1, (ull)wzx.x); fma2(az[1][1], xp1, (ull)wzx.y);
                        fma2(az[0][0], hp0, (ull)wzh.x); fma2(az[0][1], hp0, (ull)wzh.y);
                        fma2(az[1][0], hp1, (ull)wzh.x); fma2(az[1][1], hp1, (ull)wzh.y);
                        fma2(ai[0][0], xp0, (ull)wnx.x); fma2(ai[0][1], xp0, (ull)wnx.y);
                        fma2(ai[1][0], xp1, (ull)wnx.x); fma2(ai[1][1], xp1, (ull)wnx.y);
                        fma2(ah[0][0], hp0, (ull)wnh.x); fma2(ah[0][1], hp0, (ull)wnh.y);
                        fma2(ah[1][0], hp1, (ull)wnh.x); fma2(ah[1][1], hp1, (ull)wnh.y);
                    }
                }
                int c0 = g_cq * 4;
                #pragma unroll
                for (int cc = 0; cc < 4; ++cc) {
                    hold0[cc] = s_xh[g_p0][32 + c0 + cc];
                    hold1[cc] = s_xh[g_p1][32 + c0 + cc];
                }
            }
            // h-row readers/writers of a row-tile live in one warp -> warp sync suffices
            __syncwarp();
            if (tid < 216) {
                int c0 = g_cq * 4;
                float rr0[4], rr1[4], zz0[4], zz1[4], ii0[4], ii1[4], hh0[4], hh1[4];
                unpack2(ar[0][0], rr0[0], rr0[1]); unpack2(ar[0][1], rr0[2], rr0[3]);
                unpack2(ar[1][0], rr1[0], rr1[1]); unpack2(ar[1][1], rr1[2], rr1[3]);
                unpack2(az[0][0], zz0[0], zz0[1]); unpack2(az[0][1], zz0[2], zz0[3]);
                unpack2(az[1][0], zz1[0], zz1[1]); unpack2(az[1][1], zz1[2], zz1[3]);
                unpack2(ai[0][0], ii0[0], ii0[1]); unpack2(ai[0][1], ii0[2], ii0[3]);
                unpack2(ai[1][0], ii1[0], ii1[1]); unpack2(ai[1][1], ii1[2], ii1[3]);
                unpack2(ah[0][0], hh0[0], hh0[1]); unpack2(ah[0][1], hh0[2], hh0[3]);
                unpack2(ah[1][0], hh1[0], hh1[1]); unpack2(ah[1][1], hh1[2], hh1[3]);
                #pragma unroll
                for (int cc = 0; cc < 4; ++cc) {
                    int c = c0 + cc;
                    float brz_r = s_brz[g_ty][c], brz_z = s_brz[g_ty][32 + c];
                    float bni = s_bni[g_ty][c], bnh = s_bnh[g_ty][c];
                    {
                        float r = sigf(rr0[cc] + brz_r);
                        float z = sigf(zz0[cc] + brz_z);
                        float ng = tanh_fast(ii0[cc] + bni + r * (hh0[cc] + bnh));
                        s_xh[g_p0][32 + c] = ng + z * (hold0[cc] - ng);
                    }
                    {
                        float r = sigf(rr1[cc] + brz_r);
                        float z = sigf(zz1[cc] + brz_z);
                        float ng = tanh_fast(ii1[cc] + bni + r * (hh1[cc] + bnh));
                        s_xh[g_p1][32 + c] = ng + z * (hold1[cc] - ng);
                    }
                }
            }
            // no end-of-step barrier: next S1 writes only s_in; B1 orders the rest
        }  // t loop

        __syncthreads();   // all GRU h writes visible

        // ---------- write final hidden state ----------
        for (int item = tid; item < NN * 32; item += 256) {
            int n = item >> 5, k = item & 31;
            float v = s_xh[PROW(n)][32 + k];
            if (n < NAq)
                out[((long)b * NAq + n) * 32 + k] = v;
            else
                out[(long)B * NAq * 32 + ((long)b * NMe + (n - NAq)) * 32 + k] = v;
        }
        __syncthreads();
    }  // b loop
}

extern "C" void kernel_launch(void* const* d_in, const int* in_sizes, int n_in,
                              void* d_out, int out_size) {
    const float* X_aqi  = (const float*)d_in[0];
    const float* X_meo  = (const float*)d_in[1];
    const float* ctxf   = (const float*)d_in[2];
    const float* adj    = (const float*)d_in[3];
    const float* adjn   = (const float*)d_in[4];
    const float* e_aid  = (const float*)d_in[5];
    const float* e_amo  = (const float*)d_in[6];
    const float* e_awd  = (const float*)d_in[7];
    const float* e_ahr  = (const float*)d_in[8];
    const float* e_mwi  = (const float*)d_in[9];
    const float* e_mid  = (const float*)d_in[10];
    const float* e_mmo  = (const float*)d_in[11];
    const float* e_mwd  = (const float*)d_in[12];
    const float* e_mhr  = (const float*)d_in[13];
    const float* W_xa   = (const float*)d_in[14];
    const float* W_xm   = (const float*)d_in[15];
    const float* W_ua   = (const float*)d_in[16];
    const float* W_um   = (const float*)d_in[17];
    const float* a_aa   = (const float*)d_in[18];
    const float* a_am   = (const float*)d_in[19];
    const float* a_ma   = (const float*)d_in[20];
    const float* a_mm   = (const float*)d_in[21];
    const float* wih_a  = (const float*)d_in[22];
    const float* whh_a  = (const float*)d_in[23];
    const float* bih_a  = (const float*)d_in[24];
    const float* bhh_a  = (const float*)d_in[25];
    const float* wih_m  = (const float*)d_in[26];
    const float* whh_m  = (const float*)d_in[27];
    const float* bih_m  = (const float*)d_in[28];
    const float* bhh_m  = (const float*)d_in[29];
    const int*   Xae    = (const int*)d_in[30];
    const int*   Xme    = (const int*)d_in[31];
    float* out = (float*)d_out;

    int B = in_sizes[0] / (TT * NAq * 6);
    int grid = (B >= 512) ? 512 : B;

    prep_weights<<<48, 256>>>(wih_a, whh_a, wih_m, whh_m);
    chgat_gru_kernel<<<grid, 256>>>(
        X_aqi, X_meo, ctxf, adj, adjn,
        e_aid, e_amo, e_awd, e_ahr, e_mwi, e_mid, e_mmo, e_mwd, e_mhr,
        W_xa, W_xm, W_ua, W_um, a_aa, a_am, a_ma, a_mm,
        bih_a, bhh_a, bih_m, bhh_m,
        Xae, Xme, out, B);
}

// round 14
// speedup vs baseline: 2.4634x; 1.2044x over previous
#include <cuda_runtime.h>

static __device__ __forceinline__ float sigf(float x) {
    return 1.f / (1.f + __expf(-x));
}
static __device__ __forceinline__ float tanh_fast(float x) {
    return 1.f - 2.f / (__expf(2.f * x) + 1.f);
}

typedef unsigned long long ull;
static __device__ __forceinline__ void fma2(ull& d, ull a, ull b) {
    asm("fma.rn.f32x2 %0, %1, %2, %0;" : "+l"(d) : "l"(a), "l"(b));
}
static __device__ __forceinline__ ull bcast2(float x) {
    ull r;
    asm("mov.b64 %0, {%1, %1};" : "=l"(r) : "r"(__float_as_uint(x)));
    return r;
}
static __device__ __forceinline__ void unpack2(ull v, float& lo, float& hi) {
    unsigned a, b;
    asm("mov.b64 {%0, %1}, %2;" : "=r"(a), "=r"(b) : "l"(v));
    lo = __uint_as_float(a); hi = __uint_as_float(b);
}

#define TT 48
#define NAq 35
#define NMe 18
#define NN 53
#define ESTRIDE 56
#define PROW(n) ((n) + ((n) >= NAq ? 1 : 0))
#define XH_STRIDE 68

// Transposed GRU weights: [ty][mat(6)][k(32)][c(32)]
__device__ __align__(16) float g_wT[2 * 6 * 32 * 32];

__global__ void prep_weights(const float* __restrict__ wih_a, const float* __restrict__ whh_a,
                             const float* __restrict__ wih_m, const float* __restrict__ whh_m) {
    int i = blockIdx.x * 256 + threadIdx.x;
    if (i < 12288) {
        int c = i & 31;
        int k = (i >> 5) & 31;
        int m = (i >> 10) % 6;
        int ty = i / 6144;
        const float* W = (m & 1) ? (ty ? whh_m : whh_a) : (ty ? wih_m : wih_a);
        int gate = m >> 1;
        g_wT[i] = W[(gate * 32 + c) * 32 + k];
    }
}

__global__ __launch_bounds__(256, 3)
void chgat_gru_kernel(
    const float* __restrict__ X_aqi, const float* __restrict__ X_meo,
    const float* __restrict__ ctxf,  const float* __restrict__ adj,
    const float* __restrict__ adjn,
    const float* __restrict__ e_aid, const float* __restrict__ e_amo,
    const float* __restrict__ e_awd, const float* __restrict__ e_ahr,
    const float* __restrict__ e_mwi, const float* __restrict__ e_mid,
    const float* __restrict__ e_mmo, const float* __restrict__ e_mwd,
    const float* __restrict__ e_mhr,
    const float* __restrict__ W_xa,  const float* __restrict__ W_xm,
    const float* __restrict__ W_ua,  const float* __restrict__ W_um,
    const float* __restrict__ a_aa,  const float* __restrict__ a_am,
    const float* __restrict__ a_ma,  const float* __restrict__ a_mm,
    const float* __restrict__ bih_a, const float* __restrict__ bhh_a,
    const float* __restrict__ bih_m, const float* __restrict__ bhh_m,
    const int*   __restrict__ Xae,   const int*   __restrict__ Xme,
    float* __restrict__ out, int B)
{
    __shared__ __align__(16) float s_xh[56][XH_STRIDE];
    __shared__ __align__(16) float s_attri[NN][36];
    __shared__ __align__(16) float s_e[NN * ESTRIDE];
    __shared__ float s_in[NN][14];
    __shared__ float s_sd[4][NN];
    __shared__ float s_ctxs[4][NN];
    __shared__ float s_ctxd[4][NN];
    __shared__ __align__(16) float s_as[4][32];
    __shared__ __align__(16) float s_ad[4][32];
    __shared__ float s_c[4];
    __shared__ unsigned s_mask[NN][2];
    __shared__ float s_brz[2][64];
    __shared__ float s_bni[2][32];
    __shared__ float s_bnh[2][32];
    __shared__ float s_Wua[14*32], s_Wum[14*32], s_Wxa[6*32], s_Wxm[4*32];
    __shared__ float s_emb[300];

    const int tid = threadIdx.x;

    // ---------------- one-time per-block init ----------------
    for (int i = tid; i < 14*32; i += 256) { s_Wua[i] = W_ua[i]; s_Wum[i] = W_um[i]; }
    for (int i = tid; i < 6*32;  i += 256) s_Wxa[i] = W_xa[i];
    for (int i = tid; i < 4*32;  i += 256) s_Wxm[i] = W_xm[i];
    for (int i = tid; i < 64; i += 256) {
        s_brz[0][i] = bih_a[i] + bhh_a[i];
        s_brz[1][i] = bih_m[i] + bhh_m[i];
    }
    for (int i = tid; i < 32; i += 256) {
        s_bni[0][i] = bih_a[64 + i]; s_bnh[0][i] = bhh_a[64 + i];
        s_bni[1][i] = bih_m[64 + i]; s_bnh[1][i] = bhh_m[64 + i];
    }
    for (int i = tid; i < 70; i += 256) s_emb[i]       = e_aid[i];
    for (int i = tid; i < 26; i += 256) s_emb[70 + i]  = e_amo[i];
    for (int i = tid; i < 14; i += 256) s_emb[96 + i]  = e_awd[i];
    for (int i = tid; i < 48; i += 256) s_emb[110 + i] = e_ahr[i];
    for (int i = tid; i < 18; i += 256) s_emb[158 + i] = e_mwi[i];
    for (int i = tid; i < 36; i += 256) s_emb[176 + i] = e_mid[i];
    for (int i = tid; i < 26; i += 256) s_emb[212 + i] = e_mmo[i];
    for (int i = tid; i < 14; i += 256) s_emb[238 + i] = e_mwd[i];
    for (int i = tid; i < 48; i += 256) s_emb[252 + i] = e_mhr[i];
    for (int i = tid; i < 128; i += 256) {
        int v = i >> 5, j = i & 31;
        const float* av = (v == 0) ? a_aa : (v == 1) ? a_am : (v == 2) ? a_ma : a_mm;
        s_as[v][j] = av[j];
        s_ad[v][j] = av[92 + j];
    }
    if (tid < 4) {
        const float* av = (tid == 0) ? a_aa : (tid == 1) ? a_am : (tid == 2) ? a_ma : a_mm;
        s_c[tid] = av[184];
    }
    if (tid < NN) {
        unsigned m0 = 0, m1 = 0;
        for (int j = 0; j < 32; ++j)  if (adj[tid * NN + j] > 0.f) m0 |= (1u << j);
        for (int j = 32; j < NN; ++j) if (adj[tid * NN + j] > 0.f) m1 |= (1u << (j - 32));
        s_mask[tid][0] = m0; s_mask[tid][1] = m1;
    }
    for (int item = tid; item < 4 * NN; item += 256) {
        int v = item / NN, n = item % NN;
        const float* av = (v == 0) ? a_aa : (v == 1) ? a_am : (v == 2) ? a_ma : a_mm;
        float s1 = 0.f, s2 = 0.f;
        for (int c = 0; c < 60; ++c) {
            float cv = ctxf[n * 60 + c];
            s1 = fmaf(cv, av[32 + c], s1);
            s2 = fmaf(cv, av[124 + c], s2);
        }
        s_ctxs[v][n] = s1; s_ctxd[v][n] = s2;
    }
    __syncthreads();

    const int wid = tid >> 5, lane = tid & 31;
    // GRU tile coords (tid < 216): 27 row-pairs x 8 col-quads
    const int g_rt = tid >> 3, g_cq = tid & 7;
    const int g_p0 = 2 * g_rt, g_p1 = 2 * g_rt + 1;
    const int g_ty = (g_rt < 18) ? 0 : 1;
    const longlong2* g_w2 = (const longlong2*)g_wT + g_ty * 1536 + g_cq;
    // att tile coords (tid < 216): 27 row-pairs x 8 col-quads
    const int a_p = tid >> 3, a_hq = tid & 7;
    const int a_r0 = a_p, a_r1 = a_p + 27;

    for (int b = blockIdx.x; b < B; b += gridDim.x) {
        for (int i = tid; i < 56 * XH_STRIDE; i += 256) ((float*)s_xh)[i] = 0.f;
        __syncthreads();

        for (int t = 0; t < TT; ++t) {
            // ---------- S1: load x + embeddings into s_in ----------
            {
                const long bt = (long)b * TT + t;
                const float* xa = X_aqi + bt * (NAq * 6);
                for (int i = tid; i < NAq * 6; i += 256) s_in[i / 6][i % 6] = xa[i];
                const float* xm = X_meo + bt * (NMe * 4);
                for (int i = tid; i < NMe * 4; i += 256) s_in[NAq + i / 4][i % 4] = xm[i];
                const int* ia = Xae + bt * (NAq * 4);
                for (int i = tid; i < NAq * 4; i += 256) {
                    int n = i >> 2, e = i & 3;
                    int idx = ia[i];
                    int off = (e == 0) ? 0 : (e == 1) ? 70 : (e == 2) ? 96 : 110;
                    s_in[n][6 + 2*e]     = s_emb[off + idx * 2];
                    s_in[n][6 + 2*e + 1] = s_emb[off + idx * 2 + 1];
                }
                const int* im = Xme + bt * (NMe * 5);
                for (int i = tid; i < NMe * 5; i += 256) {
                    int n = i / 5, e = i % 5;
                    int idx = im[i];
                    int off = (e == 0) ? 158 : (e == 1) ? 176 : (e == 2) ? 212 : (e == 3) ? 238 : 252;
                    s_in[NAq + n][4 + 2*e]     = s_emb[off + idx * 2];
                    s_in[NAq + n][4 + 2*e + 1] = s_emb[off + idx * 2 + 1];
                }
            }
            __syncthreads();   // B1

            // ---------- S2: feat (learned part -> s_xh x slot) + attri ----------
            for (int item = tid; item < NN * 32; item += 256) {
                int n = item >> 5, h = item & 31;
                const float* in = s_in[n];
                float f = 0.f, at = 0.f;
                if (n < NAq) {
                    #pragma unroll
                    for (int j = 0; j < 14; ++j) f = fmaf(in[j], s_Wua[j * 32 + h], f);
                    #pragma unroll
                    for (int j = 0; j < 6; ++j)  at = fmaf(in[j], s_Wxa[j * 32 + h], at);
                } else {
                    #pragma unroll
                    for (int j = 0; j < 14; ++j) f = fmaf(in[j], s_Wum[j * 32 + h], f);
                    #pragma unroll
                    for (int j = 0; j < 4; ++j)  at = fmaf(in[j], s_Wxm[j * 32 + h], at);
                }
                s_xh[PROW(n)][h] = f;
                s_attri[n][h] = at;
            }
            __syncthreads();   // B2

            // ---------- S3: src/dst projections (float4) ----------
            for (int item = tid; item < 4 * NN; item += 256) {
                int v = item / NN, n = item % NN;
                bool A = n < NAq;
                int vid = (v == 0) ? (A ? 0 : 2)
                        : (v == 1) ? (A ? 1 : 3)
                        : (v == 2) ? (A ? 0 : 1)
                                   : (A ? 2 : 3);
                const float4* w4 = (const float4*)((v < 2) ? s_as[vid] : s_ad[vid]);
                float acc = (v < 2) ? s_ctxs[vid][n] : s_ctxd[vid][n];
                const float4* fr4 = (const float4*)s_xh[PROW(n)];
                #pragma unroll
                for (int q = 0; q < 8; ++q) {
                    float4 fv = fr4[q], wv = w4[q];
                    acc = fmaf(fv.x, wv.x, acc);
                    acc = fmaf(fv.y, wv.y, acc);
                    acc = fmaf(fv.z, wv.z, acc);
                    acc = fmaf(fv.w, wv.w, acc);
                }
                s_sd[v][n] = acc;
            }
            __syncthreads();   // B3

            // ---------- S4: e + masked softmax (fused, warp per row) ----------
            for (int i = wid; i < NN; i += 8) {
                bool rtA = i < NAq;
                const float* an = adjn + i * NN;
                unsigned m0 = s_mask[i][0], m1 = s_mask[i][1];
                float srcA = s_sd[0][i], srcM = s_sd[1][i];
                float e1, e2;
                {
                    int j = lane;
                    bool ctA = j < NAq;
                    float v = (ctA ? srcA : srcM)
                            + (rtA ? s_sd[2][j] : s_sd[3][j])
                            + __ldg(an + j) * s_c[rtA ? (ctA ? 0 : 1) : (ctA ? 2 : 3)];
                    v = (v >= 0.f) ? v : 0.2f * v;
                    if (!((m0 >> j) & 1u)) v = -1e12f;
                    e1 = v;
                }
                {
                    int j = lane + 32;
                    if (j < NN) {
                        bool ctA = j < NAq;
                        float v = (ctA ? srcA : srcM)
                                + (rtA ? s_sd[2][j] : s_sd[3][j])
                                + __ldg(an + j) * s_c[rtA ? (ctA ? 0 : 1) : (ctA ? 2 : 3)];
                        v = (v >= 0.f) ? v : 0.2f * v;
                        if (!((m1 >> (j - 32)) & 1u)) v = -1e12f;
                        e2 = v;
                    } else {
                        e2 = -3e38f;
                    }
                }
                float m = fmaxf(e1, e2);
                #pragma unroll
                for (int o = 16; o; o >>= 1) m = fmaxf(m, __shfl_xor_sync(0xffffffffu, m, o));
                float p1 = __expf(e1 - m);
                float p2 = (lane + 32 < NN) ? __expf(e2 - m) : 0.f;
                float s = p1 + p2;
                #pragma unroll
                for (int o = 16; o; o >>= 1) s += __shfl_xor_sync(0xffffffffu, s, o);
                float inv = 1.f / s;
                s_e[i * ESTRIDE + lane] = p1 * inv;
                if (lane + 32 < NN) s_e[i * ESTRIDE + lane + 32] = p2 * inv;
            }
            __syncthreads();   // B4

            // ---------- S5: att @ attri -> s_xh x slot (2 rows, float4 e, f32x2) ----------
            if (tid < 216) {
                bool has1 = (a_r1 < NN);
                const float4* e0q = (const float4*)(s_e + a_r0 * ESTRIDE);
                const float4* e1q = (const float4*)(s_e + (has1 ? a_r1 : a_r0) * ESTRIDE);
                ull a00 = 0, a01 = 0, a10 = 0, a11 = 0;
                #pragma unroll 1
                for (int jq = 0; jq < 13; ++jq) {
                    float4 ev0 = e0q[jq], ev1 = e1q[jq];
                    const float es0[4] = {ev0.x, ev0.y, ev0.z, ev0.w};
                    const float es1[4] = {ev1.x, ev1.y, ev1.z, ev1.w};
                    #pragma unroll
                    for (int u = 0; u < 4; ++u) {
                        int j = jq * 4 + u;
                        longlong2 lv = *(const longlong2*)&s_attri[j][a_hq * 4];
                        ull av0 = bcast2(es0[u]);
                        ull av1 = bcast2(es1[u]);
                        fma2(a00, av0, (ull)lv.x); fma2(a01, av0, (ull)lv.y);
                        fma2(a10, av1, (ull)lv.x); fma2(a11, av1, (ull)lv.y);
                    }
                }
                {   // j = 52 remainder
                    longlong2 lv = *(const longlong2*)&s_attri[52][a_hq * 4];
                    ull av0 = bcast2(s_e[a_r0 * ESTRIDE + 52]);
                    ull av1 = bcast2(s_e[(has1 ? a_r1 : a_r0) * ESTRIDE + 52]);
                    fma2(a00, av0, (ull)lv.x); fma2(a01, av0, (ull)lv.y);
                    fma2(a10, av1, (ull)lv.x); fma2(a11, av1, (ull)lv.y);
                }
                *(longlong2*)&s_xh[PROW(a_r0)][a_hq * 4] =
                    make_longlong2((long long)a00, (long long)a01);
                if (has1)
                    *(longlong2*)&s_xh[PROW(a_r1)][a_hq * 4] =
                        make_longlong2((long long)a10, (long long)a11);
            }
            __syncthreads();   // B5

            // ---------- S6: GRU (register-tiled, 2 rows x 4 cols, f32x2) ----------
            ull ar[2][2] = {{0ull,0ull},{0ull,0ull}};
            ull az[2][2] = {{0ull,0ull},{0ull,0ull}};
            ull ai[2][2] = {{0ull,0ull},{0ull,0ull}};
            ull ah[2][2] = {{0ull,0ull},{0ull,0ull}};
            float hold0[4], hold1[4];
            if (tid < 216) {
                #pragma unroll
                for (int kq = 0; kq < 8; ++kq) {
                    float4 x0 = *(const float4*)&s_xh[g_p0][4 * kq];
                    float4 x1 = *(const float4*)&s_xh[g_p1][4 * kq];
                    float4 h0 = *(const float4*)&s_xh[g_p0][32 + 4 * kq];
                    float4 h1 = *(const float4*)&s_xh[g_p1][32 + 4 * kq];
                    const float xs0[4] = {x0.x, x0.y, x0.z, x0.w};
                    const float xs1[4] = {x1.x, x1.y, x1.z, x1.w};
                    const float hs0[4] = {h0.x, h0.y, h0.z, h0.w};
                    const float hs1[4] = {h1.x, h1.y, h1.z, h1.w};
                    #pragma unroll
                    for (int i = 0; i < 4; ++i) {
                        int k = kq * 4 + i;
                        const longlong2* wk = g_w2 + k * 8;
                        longlong2 wrx = __ldg(wk);
                        longlong2 wrh = __ldg(wk + 256);
                        longlong2 wzx = __ldg(wk + 512);
                        longlong2 wzh = __ldg(wk + 768);
                        longlong2 wnx = __ldg(wk + 1024);
                        longlong2 wnh = __ldg(wk + 1280);
                        ull xp0 = bcast2(xs0[i]), xp1 = bcast2(xs1[i]);
                        ull hp0 = bcast2(hs0[i]), hp1 = bcast2(hs1[i]);
                        fma2(ar[0][0], xp0, (ull)wrx.x); fma2(ar[0][1], xp0, (ull)wrx.y);
                        fma2(ar[1][0], xp1, (ull)wrx.x); fma2(ar[1][1], xp1, (ull)wrx.y);
                        fma2(ar[0][0], hp0, (ull)wrh.x); fma2(ar[0][1], hp0, (ull)wrh.y);
                        fma2(ar[1][0], hp1, (ull)wrh.x); fma2(ar[1][1], hp1, (ull)wrh.y);
                        fma2(az[0][0], xp0, (ull)wzx.x); fma2(az[0][1], xp0, (ull)wzx.y);
                        fma2(az[1][0], xp1, (ull)wzx.x); fma2(az[1][1], xp1, (ull)wzx.y);
                        fma2(az[0][0], hp0, (ull)wzh.x); fma2(az[0][1], hp0, (ull)wzh.y);
                        fma2(az[1][0], hp1, (ull)wzh.x); fma2(az[1][1], hp1, (ull)wzh.y);
                        fma2(ai[0][0], xp0, (ull)wnx.x); fma2(ai[0][1], xp0, (ull)wnx.y);
                        fma2(ai[1][0], xp1, (ull)wnx.x); fma2(ai[1][1], xp1, (ull)wnx.y);
                        fma2(ah[0][0], hp0, (ull)wnh.x); fma2(ah[0][1], hp0, (ull)wnh.y);
                        fma2(ah[1][0], hp1, (ull)wnh.x); fma2(ah[1][1], hp1, (ull)wnh.y);
                    }
                }
                int c0 = g_cq * 4;
                #pragma unroll
                for (int cc = 0; cc < 4; ++cc) {
                    hold0[cc] = s_xh[g_p0][32 + c0 + cc];
                    hold1[cc] = s_xh[g_p1][32 + c0 + cc];
                }
            }
            // h-row readers/writers of a row-tile live in one warp -> warp sync suffices
            __syncwarp();
            if (tid < 216) {
                int c0 = g_cq * 4;
                float rr0[4], rr1[4], zz0[4], zz1[4], ii0[4], ii1[4], hh0[4], hh1[4];
                unpack2(ar[0][0], rr0[0], rr0[1]); unpack2(ar[0][1], rr0[2], rr0[3]);
                unpack2(ar[1][0], rr1[0], rr1[1]); unpack2(ar[1][1], rr1[2], rr1[3]);
                unpack2(az[0][0], zz0[0], zz0[1]); unpack2(az[0][1], zz0[2], zz0[3]);
                unpack2(az[1][0], zz1[0], zz1[1]); unpack2(az[1][1], zz1[2], zz1[3]);
                unpack2(ai[0][0], ii0[0], ii0[1]); unpack2(ai[0][1], ii0[2], ii0[3]);
                unpack2(ai[1][0], ii1[0], ii1[1]); unpack2(ai[1][1], ii1[2], ii1[3]);
                unpack2(ah[0][0], hh0[0], hh0[1]); unpack2(ah[0][1], hh0[2], hh0[3]);
                unpack2(ah[1][0], hh1[0], hh1[1]); unpack2(ah[1][1], hh1[2], hh1[3]);
                #pragma unroll
                for (int cc = 0; cc < 4; ++cc) {
                    int c = c0 + cc;
                    float brz_r = s_brz[g_ty][c], brz_z = s_brz[g_ty][32 + c];
                    float bni = s_bni[g_ty][c], bnh = s_bnh[g_ty][c];
                    {
                        float r = sigf(rr0[cc] + brz_r);
                        float z = sigf(zz0[cc] + brz_z);
                        float ng = tanh_fast(ii0[cc] + bni + r * (hh0[cc] + bnh));
                        s_xh[g_p0][32 + c] = ng + z * (hold0[cc] - ng);
                    }
                    {
                        float r = sigf(rr1[cc] + brz_r);
                        float z = sigf(zz1[cc] + brz_z);
                        float ng = tanh_fast(ii1[cc] + bni + r * (hh1[cc] + bnh));
                        s_xh[g_p1][32 + c] = ng + z * (hold1[cc] - ng);
                    }
                }
            }
            // no end-of-step barrier: next S1 writes only s_in; B1 orders the rest
        }  // t loop

        __syncthreads();   // all GRU h writes visible

        // ---------- write final hidden state ----------
        for (int item = tid; item < NN * 32; item += 256) {
            int n = item >> 5, k = item & 31;
            float v = s_xh[PROW(n)][32 + k];
            if (n < NAq)
                out[((long)b * NAq + n) * 32 + k] = v;
            else
                out[(long)B * NAq * 32 + ((long)b * NMe + (n - NAq)) * 32 + k] = v;
        }
        __syncthreads();
    }  // b loop
}

extern "C" void kernel_launch(void* const* d_in, const int* in_sizes, int n_in,
                              void* d_out, int out_size) {
    const float* X_aqi  = (const float*)d_in[0];
    const float* X_meo  = (const float*)d_in[1];
    const float* ctxf   = (const float*)d_in[2];
    const float* adj    = (const float*)d_in[3];
    const float* adjn   = (const float*)d_in[4];
    const float* e_aid  = (const float*)d_in[5];
    const float* e_amo  = (const float*)d_in[6];
    const float* e_awd  = (const float*)d_in[7];
    const float* e_ahr  = (const float*)d_in[8];
    const float* e_mwi  = (const float*)d_in[9];
    const float* e_mid  = (const float*)d_in[10];
    const float* e_mmo  = (const float*)d_in[11];
    const float* e_mwd  = (const float*)d_in[12];
    const float* e_mhr  = (const float*)d_in[13];
    const float* W_xa   = (const float*)d_in[14];
    const float* W_xm   = (const float*)d_in[15];
    const float* W_ua   = (const float*)d_in[16];
    const float* W_um   = (const float*)d_in[17];
    const float* a_aa   = (const float*)d_in[18];
    const float* a_am   = (const float*)d_in[19];
    const float* a_ma   = (const float*)d_in[20];
    const float* a_mm   = (const float*)d_in[21];
    const float* wih_a  = (const float*)d_in[22];
    const float* whh_a  = (const float*)d_in[23];
    const float* bih_a  = (const float*)d_in[24];
    const float* bhh_a  = (const float*)d_in[25];
    const float* wih_m  = (const float*)d_in[26];
    const float* whh_m  = (const float*)d_in[27];
    const float* bih_m  = (const float*)d_in[28];
    const float* bhh_m  = (const float*)d_in[29];
    const int*   Xae    = (const int*)d_in[30];
    const int*   Xme    = (const int*)d_in[31];
    float* out = (float*)d_out;

    int B = in_sizes[0] / (TT * NAq * 6);
    // One resident wave: 152 SMs x 3 blocks/SM = 456 slots.
    // grid=512 caused a 56-block straggler wave (wall = 4 batch-rounds);
    // grid=456 gives ceil(1024/456)=3 rounds, the integral floor at occ=3.
    int grid = (B >= 456) ? 456 : B;

    prep_weights<<<48, 256>>>(wih_a, whh_a, wih_m, whh_m);
    chgat_gru_kernel<<<grid, 256>>>(
        X_aqi, X_meo, ctxf, adj, adjn,
        e_aid, e_amo, e_awd, e_ahr, e_mwi, e_mid, e_mmo, e_mwd, e_mhr,
        W_xa, W_xm, W_ua, W_um, a_aa, a_am, a_ma, a_mm,
        bih_a, bhh_a, bih_m, bhh_m,
        Xae, Xme, out, B);
}